// round 2
// baseline (speedup 1.0000x reference)
#include <cuda_runtime.h>

#define NA_MAX 200000
#define COULOMB 14.399645478425668
#define PEXP 0.23
#define A0C 0.4685

// Scratch (no cudaMalloc allowed): compressed atom types + 16-entry pair table.
__device__ unsigned char g_type_u8[NA_MAX];

struct PairC { float4 a; float4 b; float4 c; };  // a=(factor, rc, A/3, B/4)  b=(C, da0, da1, da2)  c=(da3,-,-,-)
__device__ PairC g_pair[16];

// ---------------- prep: 16 pair-type constant rows (double precision) ----------------
__global__ void prep_pairs(const float* __restrict__ cov, const float* __restrict__ anum) {
    int t = threadIdx.x;
    if (t >= 16) return;
    int ti = t >> 2, tj = t & 3;
    double zi = (double)anum[ti], zj = (double)anum[tj];
    double rc = (double)cov[ti] + (double)cov[tj];
    double a  = A0C / (pow(zi, PEXP) + pow(zj, PEXP));
    const double cc[4] = {0.02817, 0.28022, 0.50986, 0.18175};
    const double dd[4] = {0.20162, 0.4029, 0.94229, 3.1998};
    double da[4];
    #pragma unroll
    for (int k = 0; k < 4; k++) da[k] = dd[k] / a;
    double factor = COULOMB * zi * zj;

    double phi = 0.0, dphi = 0.0, d2phi = 0.0;
    #pragma unroll
    for (int k = 0; k < 4; k++) {
        double ex = exp(-rc * da[k]);
        phi   += cc[k] * ex;
        dphi  += -cc[k] * da[k] * ex;
        d2phi += cc[k] * da[k] * da[k] * ex;
    }
    double ec   = factor / rc * phi;
    double dec  = factor / rc * (-phi / rc + dphi);
    double d2ec = factor / rc * (d2phi - 2.0 / rc * dphi + 2.0 * phi / (rc * rc));

    double A = (-3.0 * dec + rc * d2ec) / (rc * rc);
    double B = ( 2.0 * dec - rc * d2ec) / (rc * rc * rc);
    double C = -ec + rc * dec * 0.5 - rc * rc * d2ec / 12.0;

    PairC p;
    p.a = make_float4((float)factor, (float)rc, (float)(A / 3.0), (float)(B / 4.0));
    p.b = make_float4((float)C, (float)da[0], (float)da[1], (float)da[2]);
    p.c = make_float4((float)da[3], 0.f, 0.f, 0.f);
    g_pair[t] = p;
}

// ---------------- prep: compress types to u8 (L1-resident gather table) + zero output ----------------
__global__ void prep_atoms(const int* __restrict__ types, float* __restrict__ out,
                           int n_types, int n_out) {
    int i = blockIdx.x * blockDim.x + threadIdx.x;
    if (i < n_types) g_type_u8[i] = (unsigned char)types[i];
    if (i < n_out)   out[i] = 0.0f;
}

// ---------------- main edge kernel: 4 edges/thread, vectorized streaming loads ----------------
__global__ void __launch_bounds__(256)
zbl_edges(const float4* __restrict__ rij4, const int4* __restrict__ fa4,
          const int4* __restrict__ sa4, float* __restrict__ out, int nquads) {
    int i = blockIdx.x * blockDim.x + threadIdx.x;
    if (i >= nquads) return;
    float4 r4 = rij4[i];
    int4   f4 = fa4[i];
    int4   s4 = sa4[i];
    const float* rr = &r4.x;
    const int*   ff = &f4.x;
    const int*   ss = &s4.x;
    #pragma unroll
    for (int k = 0; k < 4; k++) {
        float r  = rr[k];
        int   fa = ff[k];
        int   sa = ss[k];
        int p = ((int)g_type_u8[fa] << 2) | (int)g_type_u8[sa];
        float4 pa = g_pair[p].a;   // factor, rc, A/3, B/4
        float rc = pa.y;
        if (r <= rc) {
            float4 pb = g_pair[p].b;   // C, da0, da1, da2
            float da3 = g_pair[p].c.x;
            float e0 = __expf(-r * pb.y);
            float e1 = __expf(-r * pb.z);
            float e2 = __expf(-r * pb.w);
            float e3 = __expf(-r * da3);
            float phi = 0.02817f * e0 + 0.28022f * e1 + 0.50986f * e2 + 0.18175f * e3;
            float r2 = r * r;
            float e = pa.x * __fdividef(phi, r) + (pa.z + pa.w * r) * r2 * r + pb.x;
            atomicAdd(out + fa, 0.5f * e);
        }
    }
}

// scalar tail (E % 4 != 0 safety; E=6.4M is divisible, but stay general)
__global__ void zbl_tail(const float* __restrict__ rij, const int* __restrict__ fst,
                         const int* __restrict__ snd, float* __restrict__ out,
                         int start, int nedges) {
    int i = start + blockIdx.x * blockDim.x + threadIdx.x;
    if (i >= nedges) return;
    float r  = rij[i];
    int   fa = fst[i];
    int   sa = snd[i];
    int p = ((int)g_type_u8[fa] << 2) | (int)g_type_u8[sa];
    float4 pa = g_pair[p].a;
    if (r <= pa.y) {
        float4 pb = g_pair[p].b;
        float da3 = g_pair[p].c.x;
        float e0 = __expf(-r * pb.y);
        float e1 = __expf(-r * pb.z);
        float e2 = __expf(-r * pb.w);
        float e3 = __expf(-r * da3);
        float phi = 0.02817f * e0 + 0.28022f * e1 + 0.50986f * e2 + 0.18175f * e3;
        float r2 = r * r;
        float e = pa.x * __fdividef(phi, r) + (pa.z + pa.w * r) * r2 * r + pb.x;
        atomicAdd(out + fa, 0.5f * e);
    }
}

extern "C" void kernel_launch(void* const* d_in, const int* in_sizes, int n_in,
                              void* d_out, int out_size) {
    // metadata order: rij, covalent_radii, atomic_numbers, first_atom, second_atom,
    //                 atom_type_index, n_atoms
    const float* rij  = (const float*)d_in[0];
    const float* cov  = (const float*)d_in[1];
    const float* anum = (const float*)d_in[2];
    const int*   fst  = (const int*)d_in[3];
    const int*   snd  = (const int*)d_in[4];
    const int*   typ  = (const int*)d_in[5];
    float* out = (float*)d_out;

    int n_edges = in_sizes[0];
    int n_atoms = in_sizes[5];
    if (n_atoms > NA_MAX) n_atoms = NA_MAX;

    prep_pairs<<<1, 16>>>(cov, anum);

    int n_prep = (n_atoms > out_size) ? n_atoms : out_size;
    prep_atoms<<<(n_prep + 255) / 256, 256>>>(typ, out, n_atoms, out_size);

    int nquads = n_edges / 4;
    if (nquads > 0) {
        zbl_edges<<<(nquads + 255) / 256, 256>>>(
            (const float4*)rij, (const int4*)fst, (const int4*)snd, out, nquads);
    }
    int tail_start = nquads * 4;
    int tail = n_edges - tail_start;
    if (tail > 0) {
        zbl_tail<<<(tail + 255) / 256, 256>>>(rij, fst, snd, out, tail_start, n_edges);
    }
}

// round 5
// speedup vs baseline: 1.2935x; 1.2935x over previous
#include <cuda_runtime.h>

#define NA_MAX 200000
#define COULOMB 14.399645478425668f
#define PEXP 0.23f
#define A0C 0.4685f

// Scratch (no cudaMalloc allowed): compressed atom types + 16-entry pair table.
__device__ unsigned char g_type_u8[NA_MAX];

struct PairC { float4 a; float4 b; float4 c; };  // a=(factor, rc, A/3, B/4)  b=(C, da0, da1, da2)  c=(da3,-,-,-)
__device__ PairC g_pair[16];

// ---------------- fused prep: pair table (block 0, fp32) + type compression ----------------
__global__ void prep_fused(const float* __restrict__ cov, const float* __restrict__ anum,
                           const int* __restrict__ types, int n_types) {
    int gi = blockIdx.x * blockDim.x + threadIdx.x;
    if (gi < n_types) g_type_u8[gi] = (unsigned char)types[gi];

    // 16 pair rows, computed in fp32 (tolerance 1e-3; this costs ~1e-6)
    if (blockIdx.x == 0 && threadIdx.x < 16) {
        int t = threadIdx.x;
        int ti = t >> 2, tj = t & 3;
        float zi = anum[ti], zj = anum[tj];
        float rc = cov[ti] + cov[tj];
        float a  = A0C / (powf(zi, PEXP) + powf(zj, PEXP));
        const float cc[4] = {0.02817f, 0.28022f, 0.50986f, 0.18175f};
        const float dd[4] = {0.20162f, 0.4029f, 0.94229f, 3.1998f};
        float da[4];
        #pragma unroll
        for (int k = 0; k < 4; k++) da[k] = dd[k] / a;
        float factor = COULOMB * zi * zj;

        float phi = 0.f, dphi = 0.f, d2phi = 0.f;
        #pragma unroll
        for (int k = 0; k < 4; k++) {
            float ex = expf(-rc * da[k]);
            phi   += cc[k] * ex;
            dphi  += -cc[k] * da[k] * ex;
            d2phi += cc[k] * da[k] * da[k] * ex;
        }
        float inv_rc = 1.0f / rc;
        float ec   = factor * inv_rc * phi;
        float dec  = factor * inv_rc * (-phi * inv_rc + dphi);
        float d2ec = factor * inv_rc * (d2phi - 2.0f * inv_rc * dphi + 2.0f * phi * inv_rc * inv_rc);

        float A = (-3.0f * dec + rc * d2ec) * inv_rc * inv_rc;
        float B = ( 2.0f * dec - rc * d2ec) * inv_rc * inv_rc * inv_rc;
        float C = -ec + rc * dec * 0.5f - rc * rc * d2ec * (1.0f / 12.0f);

        PairC p;
        p.a = make_float4(factor, rc, A * (1.0f / 3.0f), B * 0.25f);
        p.b = make_float4(C, da[0], da[1], da[2]);
        p.c = make_float4(da[3], 0.f, 0.f, 0.f);
        g_pair[t] = p;
    }
}

// ---------------- main edge kernel: 4 edges/thread, smem pair table ----------------
__global__ void __launch_bounds__(256)
zbl_edges(const float4* __restrict__ rij4, const int4* __restrict__ fa4,
          const int4* __restrict__ sa4, float* __restrict__ out, int nquads) {
    __shared__ PairC s_pair[16];
    // stage 768B table into shared (192 x 4B)
    if (threadIdx.x < 192) {
        ((float*)s_pair)[threadIdx.x] = ((const float*)g_pair)[threadIdx.x];
    }
    __syncthreads();

    int i = blockIdx.x * blockDim.x + threadIdx.x;
    if (i >= nquads) return;
    float4 r4 = rij4[i];
    int4   f4 = fa4[i];
    int4   s4 = sa4[i];
    const float* rr = &r4.x;
    const int*   ff = &f4.x;
    const int*   ss = &s4.x;
    #pragma unroll
    for (int k = 0; k < 4; k++) {
        float r  = rr[k];
        int   fa = ff[k];
        int   sa = ss[k];
        int p = ((int)g_type_u8[fa] << 2) | (int)g_type_u8[sa];
        float4 pa = s_pair[p].a;   // factor, rc, A/3, B/4
        float rc = pa.y;
        if (r <= rc) {
            float4 pb = s_pair[p].b;   // C, da0, da1, da2
            float da3 = s_pair[p].c.x;
            float e0 = __expf(-r * pb.y);
            float e1 = __expf(-r * pb.z);
            float e2 = __expf(-r * pb.w);
            float e3 = __expf(-r * da3);
            float phi = 0.02817f * e0 + 0.28022f * e1 + 0.50986f * e2 + 0.18175f * e3;
            float r2 = r * r;
            float e = pa.x * __fdividef(phi, r) + (pa.z + pa.w * r) * r2 * r + pb.x;
            atomicAdd(out + fa, 0.5f * e);
        }
    }
}

// scalar tail (E % 4 != 0 safety)
__global__ void zbl_tail(const float* __restrict__ rij, const int* __restrict__ fst,
                         const int* __restrict__ snd, float* __restrict__ out,
                         int start, int nedges) {
    int i = start + blockIdx.x * blockDim.x + threadIdx.x;
    if (i >= nedges) return;
    float r  = rij[i];
    int   fa = fst[i];
    int   sa = snd[i];
    int p = ((int)g_type_u8[fa] << 2) | (int)g_type_u8[sa];
    float4 pa = g_pair[p].a;
    if (r <= pa.y) {
        float4 pb = g_pair[p].b;
        float da3 = g_pair[p].c.x;
        float e0 = __expf(-r * pb.y);
        float e1 = __expf(-r * pb.z);
        float e2 = __expf(-r * pb.w);
        float e3 = __expf(-r * da3);
        float phi = 0.02817f * e0 + 0.28022f * e1 + 0.50986f * e2 + 0.18175f * e3;
        float r2 = r * r;
        float e = pa.x * __fdividef(phi, r) + (pa.z + pa.w * r) * r2 * r + pb.x;
        atomicAdd(out + fa, 0.5f * e);
    }
}

extern "C" void kernel_launch(void* const* d_in, const int* in_sizes, int n_in,
                              void* d_out, int out_size) {
    // metadata order: rij, covalent_radii, atomic_numbers, first_atom, second_atom,
    //                 atom_type_index, n_atoms
    const float* rij  = (const float*)d_in[0];
    const float* cov  = (const float*)d_in[1];
    const float* anum = (const float*)d_in[2];
    const int*   fst  = (const int*)d_in[3];
    const int*   snd  = (const int*)d_in[4];
    const int*   typ  = (const int*)d_in[5];
    float* out = (float*)d_out;

    int n_edges = in_sizes[0];
    int n_atoms = in_sizes[5];
    if (n_atoms > NA_MAX) n_atoms = NA_MAX;

    // zero output via graph-capturable memset node
    cudaMemsetAsync(out, 0, (size_t)out_size * sizeof(float));

    prep_fused<<<(n_atoms + 255) / 256, 256>>>(cov, anum, typ, n_atoms);

    int nquads = n_edges / 4;
    if (nquads > 0) {
        zbl_edges<<<(nquads + 255) / 256, 256>>>(
            (const float4*)rij, (const int4*)fst, (const int4*)snd, out, nquads);
    }
    int tail_start = nquads * 4;
    int tail = n_edges - tail_start;
    if (tail > 0) {
        zbl_tail<<<(tail + 255) / 256, 256>>>(rij, fst, snd, out, tail_start, n_edges);
    }
}

// round 6
// speedup vs baseline: 1.5366x; 1.1879x over previous
#include <cuda_runtime.h>

#define NA_MAX 200000
#define NW 12512               // packed 2-bit type words (16 atoms/word), padded to %4
#define COULOMB 14.399645478425668f
#define PEXP 0.23f
#define A0C 0.4685f

__device__ unsigned int g_type_packed[NW];
__device__ float4 g_pairf4[48];   // 16 pairs x 3 float4: (factor,rc,A/3,B/4) (C,da0,da1,da2) (da3,-,-,-)

// ---------------- prep: pack types to 2-bit + pair table (fp32) ----------------
__global__ void prep_pack(const float* __restrict__ cov, const float* __restrict__ anum,
                          const int* __restrict__ types, int n_atoms) {
    __shared__ unsigned char s_t[4096];
    int base = blockIdx.x * 4096;
    #pragma unroll
    for (int k = 0; k < 16; k++) {
        int a = base + k * 256 + threadIdx.x;
        s_t[k * 256 + threadIdx.x] = (a < n_atoms) ? (unsigned char)types[a] : 0;
    }
    __syncthreads();
    int w = base / 16 + threadIdx.x;
    if (w < NW) {
        unsigned int word = 0;
        #pragma unroll
        for (int j = 0; j < 16; j++)
            word |= ((unsigned int)(s_t[threadIdx.x * 16 + j] & 3u)) << (j * 2);
        g_type_packed[w] = word;
    }

    if (blockIdx.x == 0 && threadIdx.x < 16) {
        int t = threadIdx.x;
        int ti = t >> 2, tj = t & 3;
        float zi = anum[ti], zj = anum[tj];
        float rc = cov[ti] + cov[tj];
        float a  = A0C / (powf(zi, PEXP) + powf(zj, PEXP));
        const float cc[4] = {0.02817f, 0.28022f, 0.50986f, 0.18175f};
        const float dd[4] = {0.20162f, 0.4029f, 0.94229f, 3.1998f};
        float da[4];
        #pragma unroll
        for (int k = 0; k < 4; k++) da[k] = dd[k] / a;
        float factor = COULOMB * zi * zj;

        float phi = 0.f, dphi = 0.f, d2phi = 0.f;
        #pragma unroll
        for (int k = 0; k < 4; k++) {
            float ex = expf(-rc * da[k]);
            phi   += cc[k] * ex;
            dphi  += -cc[k] * da[k] * ex;
            d2phi += cc[k] * da[k] * da[k] * ex;
        }
        float inv_rc = 1.0f / rc;
        float ec   = factor * inv_rc * phi;
        float dec  = factor * inv_rc * (-phi * inv_rc + dphi);
        float d2ec = factor * inv_rc * (d2phi - 2.0f * inv_rc * dphi + 2.0f * phi * inv_rc * inv_rc);

        float A = (-3.0f * dec + rc * d2ec) * inv_rc * inv_rc;
        float B = ( 2.0f * dec - rc * d2ec) * inv_rc * inv_rc * inv_rc;
        float C = -ec + rc * dec * 0.5f - rc * rc * d2ec * (1.0f / 12.0f);

        g_pairf4[t * 3 + 0] = make_float4(factor, rc, A * (1.0f / 3.0f), B * 0.25f);
        g_pairf4[t * 3 + 1] = make_float4(C, da[0], da[1], da[2]);
        g_pairf4[t * 3 + 2] = make_float4(da[3], 0.f, 0.f, 0.f);
    }
}

// ---------------- main edge kernel: SMEM-resident 2-bit type table, persistent grid ----------------
__global__ void __launch_bounds__(256)
zbl_edges(const float4* __restrict__ rij4, const int4* __restrict__ fa4,
          const int4* __restrict__ sa4, float* __restrict__ out, int nquads) {
    extern __shared__ unsigned char smem_raw[];
    unsigned int* s_types = (unsigned int*)smem_raw;           // NW*4 = 50048 B
    float4*       s_pair  = (float4*)(smem_raw + NW * 4);      // 768 B

    // cooperative table load (int4-vectorized: NW/4 = 3128 int4)
    {
        int4* dst = (int4*)s_types;
        const int4* src = (const int4*)g_type_packed;
        for (int j = threadIdx.x; j < NW / 4; j += 256) dst[j] = src[j];
        if (threadIdx.x < 48) s_pair[threadIdx.x] = g_pairf4[threadIdx.x];
    }
    __syncthreads();

    for (int i = blockIdx.x * blockDim.x + threadIdx.x; i < nquads;
         i += gridDim.x * blockDim.x) {
        float4 r4 = rij4[i];
        int4   f4 = fa4[i];
        int4   s4 = sa4[i];
        const float* rr = &r4.x;
        const int*   ff = &f4.x;
        const int*   ss = &s4.x;
        #pragma unroll
        for (int k = 0; k < 4; k++) {
            float r  = rr[k];
            int   fa = ff[k];
            int   sa = ss[k];
            int ti = (int)((s_types[fa >> 4] >> ((fa & 15) << 1)) & 3u);
            int tj = (int)((s_types[sa >> 4] >> ((sa & 15) << 1)) & 3u);
            int p3 = ((ti << 2) | tj) * 3;
            float4 pa = s_pair[p3];            // factor, rc, A/3, B/4
            if (r <= pa.y) {
                float4 pb = s_pair[p3 + 1];    // C, da0, da1, da2
                float da3 = s_pair[p3 + 2].x;
                float e0 = __expf(-r * pb.y);
                float e1 = __expf(-r * pb.z);
                float e2 = __expf(-r * pb.w);
                float e3 = __expf(-r * da3);
                float phi = 0.02817f * e0 + 0.28022f * e1 + 0.50986f * e2 + 0.18175f * e3;
                float r2 = r * r;
                float e = pa.x * __fdividef(phi, r) + (pa.z + pa.w * r) * r2 * r + pb.x;
                atomicAdd(out + fa, 0.5f * e);
            }
        }
    }
}

// scalar tail (global packed table; E % 4 != 0 safety)
__global__ void zbl_tail(const float* __restrict__ rij, const int* __restrict__ fst,
                         const int* __restrict__ snd, float* __restrict__ out,
                         int start, int nedges) {
    int i = start + blockIdx.x * blockDim.x + threadIdx.x;
    if (i >= nedges) return;
    float r  = rij[i];
    int   fa = fst[i];
    int   sa = snd[i];
    int ti = (int)((g_type_packed[fa >> 4] >> ((fa & 15) << 1)) & 3u);
    int tj = (int)((g_type_packed[sa >> 4] >> ((sa & 15) << 1)) & 3u);
    int p3 = ((ti << 2) | tj) * 3;
    float4 pa = g_pairf4[p3];
    if (r <= pa.y) {
        float4 pb = g_pairf4[p3 + 1];
        float da3 = g_pairf4[p3 + 2].x;
        float e0 = __expf(-r * pb.y);
        float e1 = __expf(-r * pb.z);
        float e2 = __expf(-r * pb.w);
        float e3 = __expf(-r * da3);
        float phi = 0.02817f * e0 + 0.28022f * e1 + 0.50986f * e2 + 0.18175f * e3;
        float r2 = r * r;
        float e = pa.x * __fdividef(phi, r) + (pa.z + pa.w * r) * r2 * r + pb.x;
        atomicAdd(out + fa, 0.5f * e);
    }
}

extern "C" void kernel_launch(void* const* d_in, const int* in_sizes, int n_in,
                              void* d_out, int out_size) {
    const float* rij  = (const float*)d_in[0];
    const float* cov  = (const float*)d_in[1];
    const float* anum = (const float*)d_in[2];
    const int*   fst  = (const int*)d_in[3];
    const int*   snd  = (const int*)d_in[4];
    const int*   typ  = (const int*)d_in[5];
    float* out = (float*)d_out;

    int n_edges = in_sizes[0];
    int n_atoms = in_sizes[5];
    if (n_atoms > NA_MAX) n_atoms = NA_MAX;

    cudaMemsetAsync(out, 0, (size_t)out_size * sizeof(float));

    int pack_blocks = (n_atoms + 4095) / 4096;
    prep_pack<<<pack_blocks, 256>>>(cov, anum, typ, n_atoms);

    const int SMEM_BYTES = NW * 4 + 768;
    static int attr_set = 0;
    if (!attr_set) {
        cudaFuncSetAttribute(zbl_edges, cudaFuncAttributeMaxDynamicSharedMemorySize, SMEM_BYTES);
        attr_set = 1;
    }

    int nquads = n_edges / 4;
    if (nquads > 0) {
        int grid = (nquads + 255) / 256;
        if (grid > 608) grid = 608;   // 4 CTAs/SM persistent (50.8KB smem each)
        zbl_edges<<<grid, 256, SMEM_BYTES>>>(
            (const float4*)rij, (const int4*)fst, (const int4*)snd, out, nquads);
    }
    int tail_start = nquads * 4;
    int tail = n_edges - tail_start;
    if (tail > 0) {
        zbl_tail<<<(tail + 255) / 256, 256>>>(rij, fst, snd, out, tail_start, n_edges);
    }
}